// round 4
// baseline (speedup 1.0000x reference)
#include <cuda_runtime.h>

// DisplacementVectorsASU — L1/HBM-bound gather + per-edge affine transform.
//
// Inputs (metadata order):
//   d_in[0] frac_coords       float32  (100000, 3)
//   d_in[1] edge_indices      int32    (2, 4000000)
//   d_in[2] symmops           float32  (4000000, 4, 4)
//   d_in[3] cell_translations float32  (4000000, 3)
// Output: float32 (4000000, 3)
//
// Design notes:
//  - frac_coords packed to a float4 table (w = don't-care) so each node gather
//    is a single LDG.128 (one 32B sector per lane). Table is L2-resident.
//  - Pack kernel is a coalesced float-granular scatter-copy (1 thread/dst float).
//  - Streaming operands (symmops, cell_translations) loaded with evict-first
//    (.cs) hints; output stored with .cs. This protects the frac table's L1/L2
//    residency against 336MB of stream traffic.
//  - cell_translations and output staged through shared memory with
//    cooperative float4 transfers (stride-3 smem access is bank-conflict-free).

#define NODE_CAP 131072
__device__ float4 g_frac4[NODE_CAP];

// Coalesced pack: dst float d -> node n = d>>2, component k = d&3.
// Writes are perfectly coalesced; reads are 3/4-dense coalesced.
__global__ __launch_bounds__(256)
void pack_frac_kernel(const float* __restrict__ frac, int n)
{
    int d = blockIdx.x * blockDim.x + threadIdx.x;
    if (d < 4 * n) {
        int node = d >> 2;
        int k    = d & 3;
        float v = (k < 3) ? __ldg(frac + 3 * node + k) : 0.0f;
        ((float*)g_frac4)[d] = v;
    }
}

__global__ __launch_bounds__(256)
void displacement_kernel(const int*    __restrict__ ei,
                         const float4* __restrict__ sym,   // 4 float4 per edge
                         const float4* __restrict__ ct4,   // ct viewed as float4
                         float4*       __restrict__ out4,  // out viewed as float4
                         int M)
{
    __shared__ float s_ct[768];    // 256 edges * 3 floats
    __shared__ float s_out[768];

    const int tid       = threadIdx.x;
    const int blockBase = blockIdx.x * 256;
    const int e         = blockBase + tid;

    // ---- cooperative float4 load of cell_translations (evict-first) ----
    {
        const long f4base = (long)blockBase * 3 / 4;     // blockBase % 4 == 0
        if (tid < 192) {
            long idx = f4base + tid;
            if (idx * 4 < (long)M * 3) {
                ((float4*)s_ct)[tid] = __ldcs(ct4 + idx);
            }
        }
    }
    __syncthreads();

    if (e < M) {
        // Edge endpoint indices (two coalesced streams, no reuse)
        const int i0 = __ldcs(ei + e);
        const int i1 = __ldcs(ei + M + e);

        // Node coordinate gathers — single LDG.128 each; default (cache-all)
        // policy so the table stays resident.
        const float4 fin = __ldg(g_frac4 + i0);
        const float4 fo  = __ldg(g_frac4 + i1);

        // Symmop rows 0..2 (row 3 unused) — pure stream, evict-first.
        const long sb = 4L * e;
        const float4 r0 = __ldcs(sym + sb + 0);
        const float4 r1 = __ldcs(sym + sb + 1);
        const float4 r2 = __ldcs(sym + sb + 2);

        float t0 = fmaf(r0.x, fo.x, fmaf(r0.y, fo.y, fmaf(r0.z, fo.z, r0.w)));
        float t1 = fmaf(r1.x, fo.x, fmaf(r1.y, fo.y, fmaf(r1.z, fo.z, r1.w)));
        float t2 = fmaf(r2.x, fo.x, fmaf(r2.y, fo.y, fmaf(r2.z, fo.z, r2.w)));

        const float c0 = s_ct[3 * tid + 0];
        const float c1 = s_ct[3 * tid + 1];
        const float c2 = s_ct[3 * tid + 2];

        s_out[3 * tid + 0] = fin.x - (t0 - floorf(t0) + c0);
        s_out[3 * tid + 1] = fin.y - (t1 - floorf(t1) + c1);
        s_out[3 * tid + 2] = fin.z - (t2 - floorf(t2) + c2);
    }
    __syncthreads();

    // ---- cooperative float4 store of the output (evict-first) ----
    {
        const long f4base = (long)blockBase * 3 / 4;
        if (tid < 192) {
            long idx = f4base + tid;
            if (idx * 4 < (long)M * 3) {
                __stcs(out4 + idx, ((const float4*)s_out)[tid]);
            }
        }
    }
}

extern "C" void kernel_launch(void* const* d_in, const int* in_sizes, int n_in,
                              void* d_out, int out_size)
{
    const float*  frac = (const float*) d_in[0];
    const int*    ei   = (const int*)   d_in[1];
    const float4* sym  = (const float4*)d_in[2];
    const float4* ct4  = (const float4*)d_in[3];
    float4*       out4 = (float4*)      d_out;

    const int n = in_sizes[0] / 3;      // node count
    const int M = in_sizes[1] / 2;      // edge count

    // Pack: one thread per destination float (4*n floats), coalesced.
    const int packThreads = 4 * n;
    pack_frac_kernel<<<(packThreads + 255) / 256, 256>>>(frac, n);

    const int threads = 256;
    const int blocks  = (M + threads - 1) / threads;
    displacement_kernel<<<blocks, threads>>>(ei, sym, ct4, out4, M);
}

// round 5
// speedup vs baseline: 1.3238x; 1.3238x over previous
#include <cuda_runtime.h>

// DisplacementVectorsASU — gather + per-edge affine transform, L1tex/HBM bound.
//
// Inputs (metadata order):
//   d_in[0] frac_coords       float32  (100000, 3)
//   d_in[1] edge_indices      int32    (2, 4000000)
//   d_in[2] symmops           float32  (4000000, 4, 4)
//   d_in[3] cell_translations float32  (4000000, 3)
// Output: float32 (4000000, 3)
//
// R5 design:
//  - frac_coords packed to float4 table (L2-resident) -> 1 LDG.128 per gather.
//  - DEFAULT cache policy everywhere (R4 showed .cs hints cost +24us on sm_103a).
//  - 2 edges per thread: doubles memory-level parallelism through the divergent
//    gather replays (latency/queue-bound regime per R3/R4 ncu: no unit >70%).
//  - ct/out staged via smem with coalesced float4 transfers (stride-3 smem
//    access is bank-conflict-free).

#define NODE_CAP 131072
__device__ float4 g_frac4[NODE_CAP];

// Coalesced pack: dst float d -> node d>>2, component d&3.
__global__ __launch_bounds__(256)
void pack_frac_kernel(const float* __restrict__ frac, int n)
{
    int d = blockIdx.x * blockDim.x + threadIdx.x;
    if (d < 4 * n) {
        int node = d >> 2;
        int k    = d & 3;
        float v = (k < 3) ? __ldg(frac + 3 * node + k) : 0.0f;
        ((float*)g_frac4)[d] = v;
    }
}

#define TPB   256
#define EPB   512   // edges per block (2 per thread)

__global__ __launch_bounds__(TPB)
void displacement_kernel(const int*    __restrict__ ei,
                         const float4* __restrict__ sym,   // 4 float4 per edge
                         const float4* __restrict__ ct4,
                         float4*       __restrict__ out4,
                         int M)
{
    __shared__ float s_ct[EPB * 3];
    __shared__ float s_out[EPB * 3];

    const int tid       = threadIdx.x;
    const int blockBase = blockIdx.x * EPB;

    // ---- cooperative float4 load of cell_translations (coalesced) ----
    {
        const long f4base = (long)blockBase * 3 / 4;      // EPB*3 % 4 == 0
        #pragma unroll
        for (int i = tid; i < EPB * 3 / 4; i += TPB) {
            long idx = f4base + i;
            if (idx * 4 < (long)M * 3)
                ((float4*)s_ct)[i] = __ldg(ct4 + idx);
        }
    }
    __syncthreads();

    const int e0 = blockBase + tid;
    const int e1 = e0 + TPB;
    const bool v0 = (e0 < M);
    const bool v1 = (e1 < M);

    // ---- front-batched loads: indices, gathers, symmops (max MLP) ----
    int i0a = 0, i0b = 0, i1a = 0, i1b = 0;
    if (v0) { i0a = __ldg(ei + e0); i0b = __ldg(ei + M + e0); }
    if (v1) { i1a = __ldg(ei + e1); i1b = __ldg(ei + M + e1); }

    float4 fin0 = {0,0,0,0}, fo0 = {0,0,0,0};
    float4 fin1 = {0,0,0,0}, fo1 = {0,0,0,0};
    if (v0) { fin0 = __ldg(g_frac4 + i0a); fo0 = __ldg(g_frac4 + i0b); }
    if (v1) { fin1 = __ldg(g_frac4 + i1a); fo1 = __ldg(g_frac4 + i1b); }

    float4 a0 = {0,0,0,0}, a1 = {0,0,0,0}, a2 = {0,0,0,0};
    float4 b0 = {0,0,0,0}, b1 = {0,0,0,0}, b2 = {0,0,0,0};
    if (v0) {
        const long sb = 4L * e0;
        a0 = __ldg(sym + sb + 0);
        a1 = __ldg(sym + sb + 1);
        a2 = __ldg(sym + sb + 2);
    }
    if (v1) {
        const long sb = 4L * e1;
        b0 = __ldg(sym + sb + 0);
        b1 = __ldg(sym + sb + 1);
        b2 = __ldg(sym + sb + 2);
    }

    // ---- compute + smem store ----
    if (v0) {
        float t0 = fmaf(a0.x, fo0.x, fmaf(a0.y, fo0.y, fmaf(a0.z, fo0.z, a0.w)));
        float t1 = fmaf(a1.x, fo0.x, fmaf(a1.y, fo0.y, fmaf(a1.z, fo0.z, a1.w)));
        float t2 = fmaf(a2.x, fo0.x, fmaf(a2.y, fo0.y, fmaf(a2.z, fo0.z, a2.w)));
        s_out[3 * tid + 0] = fin0.x - (t0 - floorf(t0) + s_ct[3 * tid + 0]);
        s_out[3 * tid + 1] = fin0.y - (t1 - floorf(t1) + s_ct[3 * tid + 1]);
        s_out[3 * tid + 2] = fin0.z - (t2 - floorf(t2) + s_ct[3 * tid + 2]);
    }
    if (v1) {
        const int u = tid + TPB;
        float t0 = fmaf(b0.x, fo1.x, fmaf(b0.y, fo1.y, fmaf(b0.z, fo1.z, b0.w)));
        float t1 = fmaf(b1.x, fo1.x, fmaf(b1.y, fo1.y, fmaf(b1.z, fo1.z, b1.w)));
        float t2 = fmaf(b2.x, fo1.x, fmaf(b2.y, fo1.y, fmaf(b2.z, fo1.z, b2.w)));
        s_out[3 * u + 0] = fin1.x - (t0 - floorf(t0) + s_ct[3 * u + 0]);
        s_out[3 * u + 1] = fin1.y - (t1 - floorf(t1) + s_ct[3 * u + 1]);
        s_out[3 * u + 2] = fin1.z - (t2 - floorf(t2) + s_ct[3 * u + 2]);
    }
    __syncthreads();

    // ---- cooperative float4 store of the output (coalesced) ----
    {
        const long f4base = (long)blockBase * 3 / 4;
        #pragma unroll
        for (int i = tid; i < EPB * 3 / 4; i += TPB) {
            long idx = f4base + i;
            if (idx * 4 < (long)M * 3)
                out4[idx] = ((const float4*)s_out)[i];
        }
    }
}

extern "C" void kernel_launch(void* const* d_in, const int* in_sizes, int n_in,
                              void* d_out, int out_size)
{
    const float*  frac = (const float*) d_in[0];
    const int*    ei   = (const int*)   d_in[1];
    const float4* sym  = (const float4*)d_in[2];
    const float4* ct4  = (const float4*)d_in[3];
    float4*       out4 = (float4*)      d_out;

    const int n = in_sizes[0] / 3;      // node count
    const int M = in_sizes[1] / 2;      // edge count

    const int packThreads = 4 * n;
    pack_frac_kernel<<<(packThreads + 255) / 256, 256>>>(frac, n);

    const int blocks = (M + EPB - 1) / EPB;
    displacement_kernel<<<blocks, TPB>>>(ei, sym, ct4, out4, M);
}